// round 9
// baseline (speedup 1.0000x reference)
#include <cuda_runtime.h>
#include <cstdint>

#define JAX_PARTITIONABLE 1

#define MAXP   (1024*2048)
#define NBMAX  1024
#define ITERS  1000
#define SUBN   50000
#define HB     1024
#define OUTB   1024
#define CNTB   1000

#define NB0    8192   // level-0 bins (13 bits)
#define NB1    1024   // level-1 bins (10 bits)
#define NB2    512    // level-2 bins (9 bits)

// ------------------ device scratch (self-cleaning) ------------------
__device__ int          g_n_valid;
__device__ int          g_bc[NBMAX];
__device__ int          g_idx[MAXP];
__device__ float        g_xsub[SUBN];
__device__ float        g_ysub[SUBN];
__device__ float        g_scales[ITERS];
__device__ float        g_shifts[ITERS];
__device__ int          g_counts[ITERS];        // zero invariant
__device__ unsigned int g_hist[6][NB0];         // zero invariant
__device__ unsigned int g_done[8];              // zero invariant
__device__ unsigned int g_sel_prefix;
__device__ long long    g_sel_rank;
__device__ float        g_med;
__device__ float        g_dyn;
__device__ float        g_s;
__device__ float        g_t;
__device__ float        g_part[OUTB];

// ------------------ threefry2x32 (bit-exact vs JAX) ------------------
__host__ __device__ __forceinline__ void tf2x32(unsigned int k0, unsigned int k1,
                                                unsigned int x0, unsigned int x1,
                                                unsigned int& o0, unsigned int& o1) {
    unsigned int ks2 = k0 ^ k1 ^ 0x1BD11BDAu;
    x0 += k0; x1 += k1;
#define TF_RND(r) { x0 += x1; x1 = (x1 << (r)) | (x1 >> (32 - (r))); x1 ^= x0; }
    TF_RND(13) TF_RND(15) TF_RND(26) TF_RND(6)
    x0 += k1;  x1 += ks2 + 1u;
    TF_RND(17) TF_RND(29) TF_RND(16) TF_RND(24)
    x0 += ks2; x1 += k0 + 2u;
    TF_RND(13) TF_RND(15) TF_RND(26) TF_RND(6)
    x0 += k0;  x1 += k1 + 3u;
    TF_RND(17) TF_RND(29) TF_RND(16) TF_RND(24)
    x0 += k1;  x1 += ks2 + 4u;
    TF_RND(13) TF_RND(15) TF_RND(26) TF_RND(6)
    x0 += ks2; x1 += k0 + 5u;
#undef TF_RND
    o0 = x0; o1 = x1;
}

__device__ __forceinline__ unsigned int jax_bits(unsigned int ka, unsigned int kb,
                                                 unsigned int e, unsigned int n) {
#if JAX_PARTITIONABLE
    unsigned int a, b;
    tf2x32(ka, kb, 0u, e, a, b);
    return a ^ b;
#else
    unsigned int h = n >> 1;
    unsigned int lane = (e < h) ? e : (e - h);
    unsigned int a, b;
    tf2x32(ka, kb, lane, lane + h, a, b);
    return (e < h) ? a : b;
#endif
}

static inline void jax_split2_host(unsigned int ka, unsigned int kb, unsigned int* o) {
#if JAX_PARTITIONABLE
    unsigned int a, b;
    tf2x32(ka, kb, 0u, 0u, a, b); o[0] = a; o[1] = b;
    tf2x32(ka, kb, 0u, 1u, a, b); o[2] = a; o[3] = b;
#else
    unsigned int a0, b0, a1, b1;
    tf2x32(ka, kb, 0u, 2u, a0, b0);
    tf2x32(ka, kb, 1u, 3u, a1, b1);
    o[0] = a0; o[1] = a1; o[2] = b0; o[3] = b1;
#endif
}

__device__ __forceinline__ bool maskf(float d) {
    return (d > 0.1f) && (d < 100.0f) && isfinite(d);
}
__device__ __forceinline__ float y_of(float d) {
    return __fdiv_rn(1.0f, __fadd_rn(d, 1e-6f));
}
__device__ __forceinline__ unsigned int randint_off(unsigned int hb, unsigned int lb,
                                                    unsigned int span) {
    unsigned int m = 65536u % span;
    m = (m * m) % span;
    unsigned int off = (hb % span) * m + (lb % span);
    return off % span;
}

// warp-aggregated shared-memory histogram increment
__device__ __forceinline__ void agg_add(unsigned int* sh, unsigned int bin) {
    unsigned int act = __activemask();
    unsigned int peers = __match_any_sync(act, bin);
    if ((threadIdx.x & 31) == __ffs(peers) - 1)
        atomicAdd(&sh[bin], (unsigned int)__popc(peers));
}

// exclusive scan over 256 threads via warp shuffles; wsh = shared int[8]
__device__ __forceinline__ int blk_scan256(int v, int* wsh) {
    int t = threadIdx.x, lane = t & 31, w = t >> 5;
    int incl = v;
#pragma unroll
    for (int off = 1; off < 32; off <<= 1) {
        int x = __shfl_up_sync(0xffffffffu, incl, off);
        if (lane >= off) incl += x;
    }
    if (lane == 31) wsh[w] = incl;
    __syncthreads();
    if (w == 0) {
        int s = (lane < 8) ? wsh[lane] : 0;
#pragma unroll
        for (int off = 1; off < 8; off <<= 1) {
            int x = __shfl_up_sync(0xffffffffu, s, off);
            if (lane >= off) s += x;
        }
        if (lane < 8) wsh[lane] = s;
    }
    __syncthreads();
    return (w ? wsh[w - 1] : 0) + incl - v;
}

__device__ __forceinline__ bool is_last_block(int id, unsigned int grid) {
    __threadfence();
    __shared__ unsigned int s_last;
    if (threadIdx.x == 0)
        s_last = (atomicAdd(&g_done[id], 1u) == grid - 1u) ? 1u : 0u;
    __syncthreads();
    return s_last != 0u;
}

__device__ __forceinline__ void lb_clean(int hi, int doneid, int nb) {
    __syncthreads();
    if (hi >= 0)
        for (int j = threadIdx.x; j < nb; j += 256) g_hist[hi][j] = 0u;
    if (threadIdx.x == 0) g_done[doneid] = 0u;
}

// parallel bin selection over g_hist[hi]; bins: L0=8192, L1=1024, L2=512
__device__ void choose_level(int level, int stage, int hi,
                             const float* __restrict__ dren, int P) {
    __shared__ int wsh[8];
    __shared__ int sh_b;
    __shared__ long long sh_e;
    __shared__ int sh_next;
    __shared__ unsigned int sh_tot;
    __shared__ int sh_need;
    __shared__ unsigned int sh_selkey, sh_vb;
    __shared__ unsigned int red[256];

    int t = threadIdx.x;
    int nb = (level == 0) ? NB0 : (level == 1) ? NB1 : NB2;
    int per = nb >> 8;
    int sum = 0;
    for (int j = 0; j < per; j++) sum += (int)g_hist[hi][t * per + j];
    if (t == 0) { sh_b = -1; sh_next = nb; }
    __syncthreads();
    int excl = blk_scan256(sum, wsh);
    if (t == 255) sh_tot = (unsigned int)(excl + sum);
    __syncthreads();
    long long r = g_sel_rank;
    if (r >= (long long)excl && r < (long long)(excl + sum)) {
        long long c = excl;
        for (int j = 0; j < per; j++) {
            long long h = (long long)g_hist[hi][t * per + j];
            if (r < c + h) { sh_b = t * per + j; sh_e = c; break; }
            c += h;
        }
    }
    __syncthreads();
    int b = sh_b;
    if (level == 2 && b >= 0) {
        for (int j = 0; j < per; j++) {
            int idx = t * per + j;
            if (idx > b && g_hist[hi][idx]) { atomicMin(&sh_next, idx); break; }
        }
    }
    __syncthreads();
    if (t == 0) {
        long long e = sh_e;
        int bb = b;
        long long tot = (long long)sh_tot;
        if (bb < 0) { bb = nb - 1; e = tot; }   // degenerate n==0
        long long rl = r - e;
        g_sel_rank = rl;
        if (level == 0) g_sel_prefix = (unsigned int)bb;
        else if (level == 1) g_sel_prefix = (g_sel_prefix << 10) | (unsigned int)bb;
        else {
            unsigned int selkey = (g_sel_prefix << 9) | (unsigned int)bb;
            unsigned int eq = g_hist[hi][bb];
            int n = g_n_valid;
            int need = 0;
            unsigned int vb = selkey;
            if (!(n & 1)) {
                if (rl + 1 < (long long)eq) vb = selkey;
                else if (sh_next < nb)
                    vb = (g_sel_prefix << 9) | (unsigned int)sh_next;
                else need = 1;
            }
            sh_need = need; sh_selkey = selkey; sh_vb = vb;
        }
    }
    __syncthreads();
    if (level != 2) return;

    unsigned int selkey = sh_selkey;
    unsigned int vb;
    if (sh_need) {
        // rare fallback: min key strictly greater than selkey
        float med = g_med;
        unsigned int local = 0xFFFFFFFFu;
        for (int i = t; i < P; i += 256) {
            float d = dren[i];
            if (!maskf(d)) continue;
            float y = y_of(d);
            float vv = stage ? fabsf(__fsub_rn(y, med)) : y;
            unsigned int key = __float_as_uint(vv);
            if (key > selkey && key < local) local = key;
        }
        red[t] = local;
        __syncthreads();
        for (int off = 128; off; off >>= 1) {
            if (t < off) red[t] = min(red[t], red[t + off]);
            __syncthreads();
        }
        vb = red[0];
    } else vb = sh_vb;

    if (t == 0) {
        int n = g_n_valid;
        float va = __uint_as_float(selkey);
        float med = (n & 1) ? va
            : __fadd_rn(__fmul_rn(va, 0.5f), __fmul_rn(__uint_as_float(vb), 0.5f));
        if (stage == 0) {
            g_med = med;
            g_sel_rank = (n > 0) ? (long long)((n - 1) / 2) : 0ll;
            g_sel_prefix = 0u;
        } else {
            float dyn = __fmul_rn(med, 0.5f);
            if (dyn < 1e-5f) dyn = 0.01f;
            g_dyn = dyn;
        }
    }
}

// ------------------ kernels ------------------
// y compute+store, per-block valid count, stage0 L0 hist (13-bit);
// LB: scan g_bc, set n_valid/rank, choose L0s0, clean
__global__ void __launch_bounds__(256)
k_fused1(const float* __restrict__ dren, float* __restrict__ yout, int P, int NB) {
    __shared__ unsigned int sh[NB0];
    __shared__ int wsh[8];
    __shared__ int sh_tot;
    int t = threadIdx.x;
    for (int j = t; j < NB0; j += 256) sh[j] = 0u;
    __syncthreads();
    int s0 = blockIdx.x * 2048 + t * 8;
    int cnt = 0;
    if (s0 + 8 <= P) {
        float4 a = *(const float4*)(dren + s0);
        float4 b = *(const float4*)(dren + s0 + 4);
        float dd[8] = {a.x, a.y, a.z, a.w, b.x, b.y, b.z, b.w};
#pragma unroll
        for (int k = 0; k < 8; k++) {
            float y = y_of(dd[k]);
            yout[s0 + k] = y;
            if (maskf(dd[k])) { cnt++; agg_add(sh, __float_as_uint(y) >> 19); }
        }
    } else {
        for (int i = s0; i < P && i < s0 + 8; i++) {
            float d = dren[i];
            float y = y_of(d);
            yout[i] = y;
            if (maskf(d)) { cnt++; agg_add(sh, __float_as_uint(y) >> 19); }
        }
    }
    int lane = t & 31, w = t >> 5;
    int v = cnt;
    for (int o = 16; o; o >>= 1) v += __shfl_down_sync(0xffffffffu, v, o);
    if (lane == 0) wsh[w] = v;
    __syncthreads();
    if (t == 0) {
        int s = 0;
        for (int j = 0; j < 8; j++) s += wsh[j];
        g_bc[blockIdx.x] = s;
    }
    __syncthreads();
    for (int j = t; j < NB0; j += 256)
        if (sh[j]) atomicAdd(&g_hist[0][j], sh[j]);

    if (!is_last_block(0, gridDim.x)) return;

    int b4[4]; int s = 0;
#pragma unroll
    for (int j = 0; j < 4; j++) {
        int ii = t * 4 + j;
        b4[j] = (ii < NB) ? g_bc[ii] : 0;
        s += b4[j];
    }
    int ex = blk_scan256(s, wsh);
    int run = ex;
#pragma unroll
    for (int j = 0; j < 4; j++) {
        int ii = t * 4 + j;
        if (ii < NB) g_bc[ii] = run;
        run += b4[j];
    }
    if (t == 255) sh_tot = ex + s;
    __syncthreads();
    if (t == 0) {
        int n = sh_tot;
        g_n_valid = n;
        g_sel_rank = (n > 0) ? (long long)((n - 1) / 2) : 0ll;
        g_sel_prefix = 0u;
    }
    __syncthreads();
    choose_level(0, 0, 0, dren, P);
    lb_clean(0, 0, NB0);
}

// stage0 L1 hist (+ scatter only if mask not dense); LB: choose L1s0, clean
__global__ void __launch_bounds__(256)
k_fused2(const float* __restrict__ dren, int P) {
    __shared__ unsigned int sh[NB1];
    __shared__ int wsh[8];
    int t = threadIdx.x;
    for (int j = t; j < NB1; j += 256) sh[j] = 0u;
    unsigned int prefix = g_sel_prefix;
    bool dense = (g_n_valid == P);     // identity permutation: skip materializing g_idx
    __syncthreads();
    int s0 = blockIdx.x * 2048 + t * 8;
    int cnt = 0;
    unsigned int bits = 0u;
    if (s0 + 8 <= P) {
        float4 a = *(const float4*)(dren + s0);
        float4 b = *(const float4*)(dren + s0 + 4);
        float dd[8] = {a.x, a.y, a.z, a.w, b.x, b.y, b.z, b.w};
#pragma unroll
        for (int k = 0; k < 8; k++) {
            if (maskf(dd[k])) {
                cnt++; bits |= (1u << k);
                unsigned int key = __float_as_uint(y_of(dd[k]));
                if ((key >> 19) == prefix) agg_add(sh, (key >> 9) & (NB1 - 1u));
            }
        }
    } else {
        for (int i = s0; i < P && i < s0 + 8; i++) {
            float d = dren[i];
            if (maskf(d)) {
                cnt++; bits |= (1u << (i - s0));
                unsigned int key = __float_as_uint(y_of(d));
                if ((key >> 19) == prefix) agg_add(sh, (key >> 9) & (NB1 - 1u));
            }
        }
    }
    if (!dense) {
        int excl = blk_scan256(cnt, wsh);
        int wpos = g_bc[blockIdx.x] + excl;
#pragma unroll
        for (int k = 0; k < 8; k++)
            if ((bits >> k) & 1u) g_idx[wpos++] = s0 + k;
    }
    __syncthreads();
    for (int j = t; j < NB1; j += 256)
        if (sh[j]) atomicAdd(&g_hist[1][j], sh[j]);

    if (!is_last_block(1, gridDim.x)) return;
    choose_level(1, 0, 1, dren, P);
    lb_clean(1, 1, NB1);
}

// stage0 L2 hist + RANSAC sampling; LB: choose L2s0 -> med, clean
__global__ void __launch_bounds__(256)
k_h20s(const float* __restrict__ dren, const float* __restrict__ dpri,
       const float* __restrict__ yout, int P, uint4 KP, uint4 KS) {
    __shared__ unsigned int sh[NB2];
    int t = threadIdx.x;
    int gid = blockIdx.x * 256 + t;
    int stride = gridDim.x * 256;
    for (int j = t; j < NB2; j += 256) sh[j] = 0u;
    unsigned int prefix = g_sel_prefix;
    unsigned int span = (unsigned int)g_n_valid;
    bool dense = (span == (unsigned int)P);
    __syncthreads();

    int P4 = P >> 2;
    const float4* dren4 = (const float4*)dren;
    for (int q = gid; q < P4; q += stride) {
        float4 a = dren4[q];
        float dd[4] = {a.x, a.y, a.z, a.w};
#pragma unroll
        for (int k = 0; k < 4; k++) {
            if (maskf(dd[k])) {
                unsigned int key = __float_as_uint(y_of(dd[k]));
                if ((key >> 9) == prefix) agg_add(sh, key & (NB2 - 1u));
            }
        }
    }
    for (int i = P4 * 4 + gid; i < P; i += stride) {
        float d = dren[i];
        if (maskf(d)) {
            unsigned int key = __float_as_uint(y_of(d));
            if ((key >> 9) == prefix) agg_add(sh, key & (NB2 - 1u));
        }
    }

    if (gid < SUBN) {
        if (span == 0u) { g_xsub[gid] = 0.f; g_ysub[gid] = 0.f; }
        else {
            unsigned int hb = jax_bits(KS.x, KS.y, (unsigned int)gid, SUBN);
            unsigned int lb = jax_bits(KS.z, KS.w, (unsigned int)gid, SUBN);
            unsigned int pos = randint_off(hb, lb, span);
            int si = dense ? (int)pos : g_idx[pos];
            g_xsub[gid] = dpri[si];
            g_ysub[gid] = yout[si];
        }
    }
    if (gid < ITERS) {
        unsigned int p0 = 0u, p1 = 0u;
        if (span != 0u) {
            p0 = randint_off(jax_bits(KP.x, KP.y, 2u * gid, 2u * ITERS),
                             jax_bits(KP.z, KP.w, 2u * gid, 2u * ITERS), span);
            p1 = randint_off(jax_bits(KP.x, KP.y, 2u * gid + 1u, 2u * ITERS),
                             jax_bits(KP.z, KP.w, 2u * gid + 1u, 2u * ITERS), span);
        }
        int i0 = (dense && span) ? (int)p0 : g_idx[p0];
        int i1 = (dense && span) ? (int)p1 : g_idx[p1];
        float x1 = dpri[i0], x2 = dpri[i1];
        float y1 = yout[i0], y2 = yout[i1];
        float sc = __fdiv_rn(__fsub_rn(y2, y1), __fadd_rn(__fsub_rn(x2, x1), 1e-8f));
        g_scales[gid] = sc;
        g_shifts[gid] = __fsub_rn(y1, __fmul_rn(sc, x1));
    }
    __syncthreads();
    for (int j = t; j < NB2; j += 256)
        if (sh[j]) atomicAdd(&g_hist[2][j], sh[j]);

    if (!is_last_block(2, gridDim.x)) return;
    choose_level(2, 0, 2, dren, P);
    lb_clean(2, 2, NB2);
}

// stage1 hist pass; LB: choose (level 2 finalizes g_dyn), clean
__global__ void __launch_bounds__(256)
k_hist1(const float* __restrict__ dren, int P, int level, int hi, int doneid) {
    __shared__ unsigned int sh[NB0];
    int t = threadIdx.x;
    int nb = (level == 0) ? NB0 : (level == 1) ? NB1 : NB2;
    for (int j = t; j < nb; j += 256) sh[j] = 0u;
    float med = g_med;
    unsigned int prefix = g_sel_prefix;
    __syncthreads();
    int gid = blockIdx.x * 256 + t;
    int stride = gridDim.x * 256;
    int P4 = P >> 2;
    const float4* dren4 = (const float4*)dren;
    for (int q = gid; q < P4; q += stride) {
        float4 a = dren4[q];
        float dd[4] = {a.x, a.y, a.z, a.w};
#pragma unroll
        for (int k = 0; k < 4; k++) {
            if (!maskf(dd[k])) continue;
            unsigned int key = __float_as_uint(fabsf(__fsub_rn(y_of(dd[k]), med)));
            if (level == 0) agg_add(sh, key >> 19);
            else if (level == 1) { if ((key >> 19) == prefix) agg_add(sh, (key >> 9) & (NB1 - 1u)); }
            else { if ((key >> 9) == prefix) agg_add(sh, key & (NB2 - 1u)); }
        }
    }
    for (int i = P4 * 4 + gid; i < P; i += stride) {
        float d = dren[i];
        if (!maskf(d)) continue;
        unsigned int key = __float_as_uint(fabsf(__fsub_rn(y_of(d), med)));
        if (level == 0) agg_add(sh, key >> 19);
        else if (level == 1) { if ((key >> 19) == prefix) agg_add(sh, (key >> 9) & (NB1 - 1u)); }
        else { if ((key >> 9) == prefix) agg_add(sh, key & (NB2 - 1u)); }
    }
    __syncthreads();
    for (int j = t; j < nb; j += 256)
        if (sh[j]) atomicAdd(&g_hist[hi][j], sh[j]);

    if (!is_last_block(doneid, gridDim.x)) return;
    choose_level(level, 1, hi, dren, P);
    lb_clean(hi, doneid, nb);
}

// RANSAC scoring; LB: argmax -> g_s,g_t, zero g_counts
__global__ void __launch_bounds__(256)
k_count() {
    __shared__ int wc[8][8];
    __shared__ int sc[256], si[256];
    int t = threadIdx.x;
    int hy = (blockIdx.x % 125) * 8;
    int seg = blockIdx.x / 125;
    int j0 = seg * (SUBN / 8), j1 = j0 + (SUBN / 8);
    float s[8], tv[8];
    int c[8] = {0, 0, 0, 0, 0, 0, 0, 0};
#pragma unroll
    for (int k = 0; k < 8; k++) { s[k] = g_scales[hy + k]; tv[k] = g_shifts[hy + k]; }
    float dyn = g_dyn;
    for (int j = j0 + t; j < j1; j += 256) {
        float x = g_xsub[j], yv = g_ysub[j];
#pragma unroll
        for (int k = 0; k < 8; k++) {
            float r = fabsf(__fsub_rn(__fadd_rn(__fmul_rn(s[k], x), tv[k]), yv));
            c[k] += (r < dyn) ? 1 : 0;
        }
    }
    int lane = t & 31, w = t >> 5;
#pragma unroll
    for (int k = 0; k < 8; k++) {
        int v = c[k];
        for (int o = 16; o; o >>= 1) v += __shfl_down_sync(0xffffffffu, v, o);
        if (lane == 0) wc[w][k] = v;
    }
    __syncthreads();
    if (t < 8) {
        int v = 0;
        for (int j = 0; j < 8; j++) v += wc[j][t];
        atomicAdd(&g_counts[hy + t], v);
    }

    if (!is_last_block(6, gridDim.x)) return;

    int best = -2, bidx = 0x7FFFFFFF;
    for (int i = t; i < ITERS; i += 256) {
        int cc = (g_scales[i] > 0.0f) ? g_counts[i] : -1;
        if (cc > best || (cc == best && i < bidx)) { best = cc; bidx = i; }
    }
    sc[t] = best; si[t] = bidx;
    __syncthreads();
    for (int off = 128; off; off >>= 1) {
        if (t < off) {
            if (sc[t + off] > sc[t] || (sc[t + off] == sc[t] && si[t + off] < si[t])) {
                sc[t] = sc[t + off]; si[t] = si[t + off];
            }
        }
        __syncthreads();
    }
    if (t == 0) {
        bool valid = sc[0] >= 0;
        float ss = valid ? g_scales[si[0]] : 1.0f;
        float tt = valid ? g_shifts[si[0]] : 0.0f;
        if (g_n_valid < 10) { ss = 1.0f; tt = 0.0f; }
        g_s = ss; g_t = tt;
    }
    __syncthreads();
    for (int i = t; i < ITERS; i += 256) g_counts[i] = 0;
    if (t == 0) g_done[6] = 0u;
}

// outputs + loss partials; LB: final loss
__global__ void __launch_bounds__(256)
k_out(const float* __restrict__ dren, const float* __restrict__ dpri,
      float* __restrict__ depth_out, float* __restrict__ o, int P) {
    __shared__ float shf[256];
    __shared__ double shd[256];
    int t = threadIdx.x;
    int gid = blockIdx.x * 256 + t;
    int stride = gridDim.x * 256;
    float s = g_s, tt = g_t;
    float acc = 0.f;
    int P4 = P >> 2;
    const float4* dren4 = (const float4*)dren;
    const float4* dpri4 = (const float4*)dpri;
    for (int q = gid; q < P4; q += stride) {
        float4 a = dren4[q];
        float4 p = dpri4[q];
        float dd[4] = {a.x, a.y, a.z, a.w};
        float pp[4] = {p.x, p.y, p.z, p.w};
#pragma unroll
        for (int k = 0; k < 4; k++) {
            float al = __fadd_rn(__fmul_rn(s, pp[k]), tt);
            depth_out[4 * q + k] = __fdiv_rn(1.0f, fmaxf(al, 1e-4f));
            if (maskf(dd[k])) acc += fabsf(__fsub_rn(al, y_of(dd[k])));
        }
    }
    for (int i = P4 * 4 + gid; i < P; i += stride) {
        float al = __fadd_rn(__fmul_rn(s, dpri[i]), tt);
        depth_out[i] = __fdiv_rn(1.0f, fmaxf(al, 1e-4f));
        if (maskf(dren[i])) acc += fabsf(__fsub_rn(al, y_of(dren[i])));
    }
    shf[t] = acc;
    __syncthreads();
    for (int off = 128; off; off >>= 1) {
        if (t < off) shf[t] += shf[t + off];
        __syncthreads();
    }
    if (t == 0) g_part[blockIdx.x] = shf[0];

    if (!is_last_block(7, gridDim.x)) return;

    double d = 0.0;
    for (int i = t; i < OUTB; i += 256) d += (double)g_part[i];
    shd[t] = d;
    __syncthreads();
    for (int off = 128; off; off >>= 1) {
        if (t < off) shd[t] += shd[t + off];
        __syncthreads();
    }
    if (t == 0) {
        int n = g_n_valid;
        int denom = (n > 1) ? n : 1;
        float l1 = (float)shd[0] / (float)denom;
        float loss = __fmul_rn(0.5f, l1);
        if (n < 100) loss = 0.0f;
        o[0] = loss;
        g_done[7] = 0u;
    }
}

// ------------------ launch ------------------
extern "C" void kernel_launch(void* const* d_in, const int* in_sizes, int n_in,
                              void* d_out, int out_size) {
    const float* dren = (const float*)d_in[0];
    const float* dpri = (const float*)d_in[1];
    float* o = (float*)d_out;
    int P = in_sizes[0];
    float* yout  = o + 1;
    float* dout2 = o + 1 + P;

    unsigned int kk[4], kp[4], ks[4];
    jax_split2_host(0u, 42u, kk);
    jax_split2_host(kk[0], kk[1], kp);
    jax_split2_host(kk[2], kk[3], ks);
    uint4 KP = make_uint4(kp[0], kp[1], kp[2], kp[3]);
    uint4 KS = make_uint4(ks[0], ks[1], ks[2], ks[3]);

    int NB = (P + 2047) / 2048;

    k_fused1<<<NB, 256>>>(dren, yout, P, NB);
    k_fused2<<<NB, 256>>>(dren, P);
    k_h20s<<<HB, 256>>>(dren, dpri, yout, P, KP, KS);
    k_hist1<<<HB, 256>>>(dren, P, 0, 3, 3);
    k_hist1<<<HB, 256>>>(dren, P, 1, 4, 4);
    k_hist1<<<HB, 256>>>(dren, P, 2, 5, 5);
    k_count<<<CNTB, 256>>>();
    k_out<<<OUTB, 256>>>(dren, dpri, dout2, o, P);
}

// round 11
// speedup vs baseline: 1.2819x; 1.2819x over previous
#include <cuda_runtime.h>
#include <cstdint>

#define JAX_PARTITIONABLE 1

#define MAXP   (1024*2048)
#define NBMAX  1024
#define ITERS  1000
#define SUBN   50000
#define HB     1024
#define OUTB   1024
#define CNTB   1000
#define NANF   0x7FC00000u

// ------------------ device scratch (self-cleaning) ------------------
__device__ int          g_n_valid;
__device__ int          g_bc[NBMAX];
__device__ int          g_idx[MAXP];
__device__ float        g_ymask[MAXP];          // y if mask else NaN
__device__ float        g_xsub[SUBN];
__device__ float        g_ysub[SUBN];
__device__ float        g_scales[ITERS];
__device__ float        g_shifts[ITERS];
__device__ int          g_counts[ITERS];        // zero invariant
__device__ unsigned int g_hist[6][2048];        // zero invariant
__device__ unsigned int g_done[8];              // zero invariant
__device__ unsigned int g_sel_prefix;
__device__ long long    g_sel_rank;
__device__ float        g_med;
__device__ float        g_dyn;
__device__ float        g_s;
__device__ float        g_t;
__device__ float        g_part[OUTB];

// ------------------ threefry2x32 (bit-exact vs JAX) ------------------
__host__ __device__ __forceinline__ void tf2x32(unsigned int k0, unsigned int k1,
                                                unsigned int x0, unsigned int x1,
                                                unsigned int& o0, unsigned int& o1) {
    unsigned int ks2 = k0 ^ k1 ^ 0x1BD11BDAu;
    x0 += k0; x1 += k1;
#define TF_RND(r) { x0 += x1; x1 = (x1 << (r)) | (x1 >> (32 - (r))); x1 ^= x0; }
    TF_RND(13) TF_RND(15) TF_RND(26) TF_RND(6)
    x0 += k1;  x1 += ks2 + 1u;
    TF_RND(17) TF_RND(29) TF_RND(16) TF_RND(24)
    x0 += ks2; x1 += k0 + 2u;
    TF_RND(13) TF_RND(15) TF_RND(26) TF_RND(6)
    x0 += k0;  x1 += k1 + 3u;
    TF_RND(17) TF_RND(29) TF_RND(16) TF_RND(24)
    x0 += k1;  x1 += ks2 + 4u;
    TF_RND(13) TF_RND(15) TF_RND(26) TF_RND(6)
    x0 += ks2; x1 += k0 + 5u;
#undef TF_RND
    o0 = x0; o1 = x1;
}

__device__ __forceinline__ unsigned int jax_bits(unsigned int ka, unsigned int kb,
                                                 unsigned int e, unsigned int n) {
#if JAX_PARTITIONABLE
    unsigned int a, b;
    tf2x32(ka, kb, 0u, e, a, b);
    return a ^ b;
#else
    unsigned int h = n >> 1;
    unsigned int lane = (e < h) ? e : (e - h);
    unsigned int a, b;
    tf2x32(ka, kb, lane, lane + h, a, b);
    return (e < h) ? a : b;
#endif
}

static inline void jax_split2_host(unsigned int ka, unsigned int kb, unsigned int* o) {
#if JAX_PARTITIONABLE
    unsigned int a, b;
    tf2x32(ka, kb, 0u, 0u, a, b); o[0] = a; o[1] = b;
    tf2x32(ka, kb, 0u, 1u, a, b); o[2] = a; o[3] = b;
#else
    unsigned int a0, b0, a1, b1;
    tf2x32(ka, kb, 0u, 2u, a0, b0);
    tf2x32(ka, kb, 1u, 3u, a1, b1);
    o[0] = a0; o[1] = a1; o[2] = b0; o[3] = b1;
#endif
}

__device__ __forceinline__ bool maskf(float d) {
    return (d > 0.1f) && (d < 100.0f) && isfinite(d);
}
__device__ __forceinline__ float y_of(float d) {
    return __fdiv_rn(1.0f, __fadd_rn(d, 1e-6f));
}
__device__ __forceinline__ unsigned int randint_off(unsigned int hb, unsigned int lb,
                                                    unsigned int span) {
    unsigned int m = 65536u % span;
    m = (m * m) % span;
    unsigned int off = (hb % span) * m + (lb % span);
    return off % span;
}

// exclusive scan over 256 threads via warp shuffles; wsh = shared int[8]
__device__ __forceinline__ int blk_scan256(int v, int* wsh) {
    int t = threadIdx.x, lane = t & 31, w = t >> 5;
    int incl = v;
#pragma unroll
    for (int off = 1; off < 32; off <<= 1) {
        int x = __shfl_up_sync(0xffffffffu, incl, off);
        if (lane >= off) incl += x;
    }
    if (lane == 31) wsh[w] = incl;
    __syncthreads();
    if (w == 0) {
        int s = (lane < 8) ? wsh[lane] : 0;
#pragma unroll
        for (int off = 1; off < 8; off <<= 1) {
            int x = __shfl_up_sync(0xffffffffu, s, off);
            if (lane >= off) s += x;
        }
        if (lane < 8) wsh[lane] = s;
    }
    __syncthreads();
    return (w ? wsh[w - 1] : 0) + incl - v;
}

__device__ __forceinline__ bool is_last_block(int id, unsigned int grid) {
    __threadfence();
    __shared__ unsigned int s_last;
    if (threadIdx.x == 0)
        s_last = (atomicAdd(&g_done[id], 1u) == grid - 1u) ? 1u : 0u;
    __syncthreads();
    return s_last != 0u;
}

__device__ __forceinline__ void lb_clean(int hi, int doneid, int nb) {
    __syncthreads();
    if (hi >= 0)
        for (int j = threadIdx.x; j < nb; j += 256) g_hist[hi][j] = 0u;
    if (threadIdx.x == 0) g_done[doneid] = 0u;
}

// parallel bin selection over g_hist[hi]; levels 0/1: 2048 bins, level 2: 1024
__device__ void choose_level(int level, int stage, int hi, int P) {
    __shared__ int wsh[8];
    __shared__ int sh_b;
    __shared__ long long sh_e;
    __shared__ int sh_next;
    __shared__ unsigned int sh_tot;
    __shared__ int sh_need;
    __shared__ unsigned int sh_selkey, sh_vb;
    __shared__ unsigned int red[256];

    int t = threadIdx.x;
    int nb = (level == 2) ? 1024 : 2048;
    int per = nb >> 8;
    unsigned int v[8];
    int sum = 0;
#pragma unroll
    for (int j = 0; j < 8; j++) {
        v[j] = (j < per) ? g_hist[hi][t * per + j] : 0u;
        sum += (int)v[j];
    }
    if (t == 0) { sh_b = -1; sh_next = nb; }
    __syncthreads();
    int excl = blk_scan256(sum, wsh);
    if (t == 255) sh_tot = (unsigned int)(excl + sum);
    __syncthreads();
    long long r = g_sel_rank;
    if (r >= (long long)excl && r < (long long)(excl + sum)) {
        long long c = excl;
        for (int j = 0; j < per; j++) {
            if (r < c + (long long)v[j]) { sh_b = t * per + j; sh_e = c; break; }
            c += (long long)v[j];
        }
    }
    __syncthreads();
    int b = sh_b;
    if (level == 2 && b >= 0) {
        for (int j = 0; j < per; j++) {
            int idx = t * per + j;
            if (idx > b && v[j]) { atomicMin(&sh_next, idx); break; }
        }
    }
    __syncthreads();
    if (t == 0) {
        long long e = sh_e;
        int bb = b;
        long long tot = (long long)sh_tot;
        if (bb < 0) { bb = nb - 1; e = tot; }   // degenerate n==0
        long long rl = r - e;
        g_sel_rank = rl;
        if (level == 0) g_sel_prefix = (unsigned int)bb;
        else if (level == 1) g_sel_prefix = (g_sel_prefix << 11) | (unsigned int)bb;
        else {
            unsigned int selkey = (g_sel_prefix << 10) | (unsigned int)bb;
            unsigned int eq = g_hist[hi][bb];
            int n = g_n_valid;
            int need = 0;
            unsigned int vb = selkey;
            if (!(n & 1)) {
                if (rl + 1 < (long long)eq) vb = selkey;
                else if (sh_next < nb)
                    vb = (g_sel_prefix << 10) | (unsigned int)sh_next;
                else need = 1;
            }
            sh_need = need; sh_selkey = selkey; sh_vb = vb;
        }
    }
    __syncthreads();
    if (level != 2) return;

    unsigned int selkey = sh_selkey;
    unsigned int vb;
    if (sh_need) {
        // rare fallback: min key strictly greater than selkey (reads ymask; no div)
        float med = g_med;
        unsigned int local = 0xFFFFFFFFu;
        for (int i = t; i < P; i += 256) {
            float ym = g_ymask[i];
            unsigned int kraw = __float_as_uint(ym);
            if (kraw >= 0x7F800000u) continue;
            unsigned int key = stage ? __float_as_uint(fabsf(__fsub_rn(ym, med))) : kraw;
            if (key > selkey && key < local) local = key;
        }
        red[t] = local;
        __syncthreads();
        for (int off = 128; off; off >>= 1) {
            if (t < off) red[t] = min(red[t], red[t + off]);
            __syncthreads();
        }
        vb = red[0];
    } else vb = sh_vb;

    if (t == 0) {
        int n = g_n_valid;
        float va = __uint_as_float(selkey);
        float med = (n & 1) ? va
            : __fadd_rn(__fmul_rn(va, 0.5f), __fmul_rn(__uint_as_float(vb), 0.5f));
        if (stage == 0) {
            g_med = med;
            g_sel_rank = (n > 0) ? (long long)((n - 1) / 2) : 0ll;
            g_sel_prefix = 0u;
        } else {
            float dyn = __fmul_rn(med, 0.5f);
            if (dyn < 1e-5f) dyn = 0.01f;
            g_dyn = dyn;
        }
    }
}

// ------------------ kernels ------------------
// THE div pass: y compute, yout (scalar: +1 offset is not 16B-aligned) + ymask
// (float4) stores, count, stage0 L0 hist; LB: scan g_bc, choose L0s0, clean
__global__ void __launch_bounds__(256)
k_fused1(const float* __restrict__ dren, float* __restrict__ yout, int P, int NB) {
    __shared__ unsigned int sh[2048];
    __shared__ int wsh[8];
    __shared__ int sh_tot;
    int t = threadIdx.x;
    for (int j = t; j < 2048; j += 256) sh[j] = 0u;
    __syncthreads();
    int s0 = blockIdx.x * 2048 + t * 8;
    int cnt = 0;
    if (s0 + 8 <= P) {
        float4 a = *(const float4*)(dren + s0);
        float4 b = *(const float4*)(dren + s0 + 4);
        float dd[8] = {a.x, a.y, a.z, a.w, b.x, b.y, b.z, b.w};
        float ym[8];
#pragma unroll
        for (int k = 0; k < 8; k++) {
            float y = y_of(dd[k]);
            yout[s0 + k] = y;                    // scalar: dest misaligned for STG.128
            bool m = maskf(dd[k]);
            ym[k] = m ? y : __uint_as_float(NANF);
            if (m) { cnt++; atomicAdd(&sh[__float_as_uint(y) >> 21], 1u); }
        }
        *(float4*)(g_ymask + s0)     = make_float4(ym[0], ym[1], ym[2], ym[3]);
        *(float4*)(g_ymask + s0 + 4) = make_float4(ym[4], ym[5], ym[6], ym[7]);
    } else {
        for (int i = s0; i < P && i < s0 + 8; i++) {
            float d = dren[i];
            float y = y_of(d);
            yout[i] = y;
            bool m = maskf(d);
            g_ymask[i] = m ? y : __uint_as_float(NANF);
            if (m) { cnt++; atomicAdd(&sh[__float_as_uint(y) >> 21], 1u); }
        }
    }
    int lane = t & 31, w = t >> 5;
    int v = cnt;
    for (int o = 16; o; o >>= 1) v += __shfl_down_sync(0xffffffffu, v, o);
    if (lane == 0) wsh[w] = v;
    __syncthreads();
    if (t == 0) {
        int s = 0;
        for (int j = 0; j < 8; j++) s += wsh[j];
        g_bc[blockIdx.x] = s;
    }
    __syncthreads();
    for (int j = t; j < 2048; j += 256)
        if (sh[j]) atomicAdd(&g_hist[0][j], sh[j]);

    if (!is_last_block(0, gridDim.x)) return;

    int b4[4]; int s = 0;
#pragma unroll
    for (int j = 0; j < 4; j++) {
        int ii = t * 4 + j;
        b4[j] = (ii < NB) ? g_bc[ii] : 0;
        s += b4[j];
    }
    int ex = blk_scan256(s, wsh);
    int run = ex;
#pragma unroll
    for (int j = 0; j < 4; j++) {
        int ii = t * 4 + j;
        if (ii < NB) g_bc[ii] = run;
        run += b4[j];
    }
    if (t == 255) sh_tot = ex + s;
    __syncthreads();
    if (t == 0) {
        int n = sh_tot;
        g_n_valid = n;
        g_sel_rank = (n > 0) ? (long long)((n - 1) / 2) : 0ll;
        g_sel_prefix = 0u;
    }
    __syncthreads();
    choose_level(0, 0, 0, P);
    lb_clean(0, 0, 2048);
}

// stage0 L1 hist from ymask (+ scatter if !dense); LB: choose L1s0, clean
__global__ void __launch_bounds__(256)
k_fused2(int P) {
    __shared__ unsigned int sh[2048];
    __shared__ int wsh[8];
    int t = threadIdx.x;
    for (int j = t; j < 2048; j += 256) sh[j] = 0u;
    unsigned int prefix = g_sel_prefix;
    bool dense = (g_n_valid == P);
    __syncthreads();
    int s0 = blockIdx.x * 2048 + t * 8;
    int cnt = 0;
    unsigned int bits = 0u;
    if (s0 + 8 <= P) {
        float4 a = *(const float4*)(g_ymask + s0);
        float4 b = *(const float4*)(g_ymask + s0 + 4);
        float ym[8] = {a.x, a.y, a.z, a.w, b.x, b.y, b.z, b.w};
#pragma unroll
        for (int k = 0; k < 8; k++) {
            unsigned int key = __float_as_uint(ym[k]);
            if (key < 0x7F800000u) {
                cnt++; bits |= (1u << k);
                if ((key >> 21) == prefix) atomicAdd(&sh[(key >> 10) & 2047u], 1u);
            }
        }
    } else {
        for (int i = s0; i < P && i < s0 + 8; i++) {
            unsigned int key = __float_as_uint(g_ymask[i]);
            if (key < 0x7F800000u) {
                cnt++; bits |= (1u << (i - s0));
                if ((key >> 21) == prefix) atomicAdd(&sh[(key >> 10) & 2047u], 1u);
            }
        }
    }
    if (!dense) {
        int excl = blk_scan256(cnt, wsh);
        int wpos = g_bc[blockIdx.x] + excl;
#pragma unroll
        for (int k = 0; k < 8; k++)
            if ((bits >> k) & 1u) g_idx[wpos++] = s0 + k;
    }
    __syncthreads();
    for (int j = t; j < 2048; j += 256)
        if (sh[j]) atomicAdd(&g_hist[1][j], sh[j]);

    if (!is_last_block(1, gridDim.x)) return;
    choose_level(1, 0, 1, P);
    lb_clean(1, 1, 2048);
}

// stage0 L2 hist (ymask) + RANSAC sampling; LB: choose L2s0 -> med, clean
__global__ void __launch_bounds__(256)
k_h20s(const float* __restrict__ dpri, const float* __restrict__ yout,
       int P, uint4 KP, uint4 KS) {
    __shared__ unsigned int sh[1024];
    int t = threadIdx.x;
    int gid = blockIdx.x * 256 + t;
    int stride = gridDim.x * 256;
    for (int j = t; j < 1024; j += 256) sh[j] = 0u;
    unsigned int prefix = g_sel_prefix;
    unsigned int span = (unsigned int)g_n_valid;
    bool dense = (span == (unsigned int)P);
    __syncthreads();

    int P4 = P >> 2;
    const float4* ym4 = (const float4*)g_ymask;
    for (int q = gid; q < P4; q += stride) {
        float4 a = ym4[q];
        float ym[4] = {a.x, a.y, a.z, a.w};
#pragma unroll
        for (int k = 0; k < 4; k++) {
            unsigned int key = __float_as_uint(ym[k]);
            if (key < 0x7F800000u && (key >> 10) == prefix)
                atomicAdd(&sh[key & 1023u], 1u);
        }
    }
    for (int i = P4 * 4 + gid; i < P; i += stride) {
        unsigned int key = __float_as_uint(g_ymask[i]);
        if (key < 0x7F800000u && (key >> 10) == prefix)
            atomicAdd(&sh[key & 1023u], 1u);
    }

    if (gid < SUBN) {
        if (span == 0u) { g_xsub[gid] = 0.f; g_ysub[gid] = 0.f; }
        else {
            unsigned int hb = jax_bits(KS.x, KS.y, (unsigned int)gid, SUBN);
            unsigned int lb = jax_bits(KS.z, KS.w, (unsigned int)gid, SUBN);
            unsigned int pos = randint_off(hb, lb, span);
            int si = dense ? (int)pos : g_idx[pos];
            g_xsub[gid] = dpri[si];
            g_ysub[gid] = yout[si];
        }
    }
    if (gid < ITERS) {
        unsigned int p0 = 0u, p1 = 0u;
        if (span != 0u) {
            p0 = randint_off(jax_bits(KP.x, KP.y, 2u * gid, 2u * ITERS),
                             jax_bits(KP.z, KP.w, 2u * gid, 2u * ITERS), span);
            p1 = randint_off(jax_bits(KP.x, KP.y, 2u * gid + 1u, 2u * ITERS),
                             jax_bits(KP.z, KP.w, 2u * gid + 1u, 2u * ITERS), span);
        }
        int i0 = (dense && span) ? (int)p0 : g_idx[p0];
        int i1 = (dense && span) ? (int)p1 : g_idx[p1];
        float x1 = dpri[i0], x2 = dpri[i1];
        float y1 = yout[i0], y2 = yout[i1];
        float sc = __fdiv_rn(__fsub_rn(y2, y1), __fadd_rn(__fsub_rn(x2, x1), 1e-8f));
        g_scales[gid] = sc;
        g_shifts[gid] = __fsub_rn(y1, __fmul_rn(sc, x1));
    }
    __syncthreads();
    for (int j = t; j < 1024; j += 256)
        if (sh[j]) atomicAdd(&g_hist[2][j], sh[j]);

    if (!is_last_block(2, gridDim.x)) return;
    choose_level(2, 0, 2, P);
    lb_clean(2, 2, 1024);
}

// stage1 hist pass from ymask; LB: choose (L2 finalizes dyn), clean
__global__ void __launch_bounds__(256)
k_hist1(int P, int level, int hi, int doneid) {
    __shared__ unsigned int sh[2048];
    int t = threadIdx.x;
    int nb = (level == 2) ? 1024 : 2048;
    for (int j = t; j < nb; j += 256) sh[j] = 0u;
    float med = g_med;
    unsigned int prefix = g_sel_prefix;
    __syncthreads();
    int gid = blockIdx.x * 256 + t;
    int stride = gridDim.x * 256;
    int P4 = P >> 2;
    const float4* ym4 = (const float4*)g_ymask;
    for (int q = gid; q < P4; q += stride) {
        float4 a = ym4[q];
        float ym[4] = {a.x, a.y, a.z, a.w};
#pragma unroll
        for (int k = 0; k < 4; k++) {
            if (__float_as_uint(ym[k]) >= 0x7F800000u) continue;
            unsigned int key = __float_as_uint(fabsf(__fsub_rn(ym[k], med)));
            if (level == 0) atomicAdd(&sh[key >> 21], 1u);
            else if (level == 1) { if ((key >> 21) == prefix) atomicAdd(&sh[(key >> 10) & 2047u], 1u); }
            else { if ((key >> 10) == prefix) atomicAdd(&sh[key & 1023u], 1u); }
        }
    }
    for (int i = P4 * 4 + gid; i < P; i += stride) {
        float ym = g_ymask[i];
        if (__float_as_uint(ym) >= 0x7F800000u) continue;
        unsigned int key = __float_as_uint(fabsf(__fsub_rn(ym, med)));
        if (level == 0) atomicAdd(&sh[key >> 21], 1u);
        else if (level == 1) { if ((key >> 21) == prefix) atomicAdd(&sh[(key >> 10) & 2047u], 1u); }
        else { if ((key >> 10) == prefix) atomicAdd(&sh[key & 1023u], 1u); }
    }
    __syncthreads();
    for (int j = t; j < nb; j += 256)
        if (sh[j]) atomicAdd(&g_hist[hi][j], sh[j]);

    if (!is_last_block(doneid, gridDim.x)) return;
    choose_level(level, 1, hi, P);
    lb_clean(hi, doneid, nb);
}

// RANSAC scoring; LB: argmax -> g_s,g_t, zero g_counts
__global__ void __launch_bounds__(256)
k_count() {
    __shared__ int wc[8][8];
    __shared__ int sc[256], si[256];
    int t = threadIdx.x;
    int hy = (blockIdx.x % 125) * 8;
    int seg = blockIdx.x / 125;
    int j0 = seg * (SUBN / 8), j1 = j0 + (SUBN / 8);
    float s[8], tv[8];
    int c[8] = {0, 0, 0, 0, 0, 0, 0, 0};
#pragma unroll
    for (int k = 0; k < 8; k++) { s[k] = g_scales[hy + k]; tv[k] = g_shifts[hy + k]; }
    float dyn = g_dyn;
    for (int j = j0 + t; j < j1; j += 256) {
        float x = g_xsub[j], yv = g_ysub[j];
#pragma unroll
        for (int k = 0; k < 8; k++) {
            float r = fabsf(__fsub_rn(__fadd_rn(__fmul_rn(s[k], x), tv[k]), yv));
            c[k] += (r < dyn) ? 1 : 0;
        }
    }
    int lane = t & 31, w = t >> 5;
#pragma unroll
    for (int k = 0; k < 8; k++) {
        int v = c[k];
        for (int o = 16; o; o >>= 1) v += __shfl_down_sync(0xffffffffu, v, o);
        if (lane == 0) wc[w][k] = v;
    }
    __syncthreads();
    if (t < 8) {
        int v = 0;
        for (int j = 0; j < 8; j++) v += wc[j][t];
        atomicAdd(&g_counts[hy + t], v);
    }

    if (!is_last_block(6, gridDim.x)) return;

    int best = -2, bidx = 0x7FFFFFFF;
    for (int i = t; i < ITERS; i += 256) {
        int cc = (g_scales[i] > 0.0f) ? g_counts[i] : -1;
        if (cc > best || (cc == best && i < bidx)) { best = cc; bidx = i; }
    }
    sc[t] = best; si[t] = bidx;
    __syncthreads();
    for (int off = 128; off; off >>= 1) {
        if (t < off) {
            if (sc[t + off] > sc[t] || (sc[t + off] == sc[t] && si[t + off] < si[t])) {
                sc[t] = sc[t + off]; si[t] = si[t + off];
            }
        }
        __syncthreads();
    }
    if (t == 0) {
        bool valid = sc[0] >= 0;
        float ss = valid ? g_scales[si[0]] : 1.0f;
        float tt = valid ? g_shifts[si[0]] : 0.0f;
        if (g_n_valid < 10) { ss = 1.0f; tt = 0.0f; }
        g_s = ss; g_t = tt;
    }
    __syncthreads();
    for (int i = t; i < ITERS; i += 256) g_counts[i] = 0;
    if (t == 0) g_done[6] = 0u;
}

// outputs (div pass 2; scalar stores — dest misaligned for STG.128) + loss; LB: final
__global__ void __launch_bounds__(256)
k_out(const float* __restrict__ dpri, float* __restrict__ depth_out,
      float* __restrict__ o, int P) {
    __shared__ float shf[256];
    __shared__ double shd[256];
    int t = threadIdx.x;
    int gid = blockIdx.x * 256 + t;
    int stride = gridDim.x * 256;
    float s = g_s, tt = g_t;
    float acc = 0.f;
    int P4 = P >> 2;
    const float4* ym4 = (const float4*)g_ymask;
    const float4* dpri4 = (const float4*)dpri;
    for (int q = gid; q < P4; q += stride) {
        float4 a = ym4[q];
        float4 p = dpri4[q];
        float ym[4] = {a.x, a.y, a.z, a.w};
        float pp[4] = {p.x, p.y, p.z, p.w};
#pragma unroll
        for (int k = 0; k < 4; k++) {
            float al = __fadd_rn(__fmul_rn(s, pp[k]), tt);
            depth_out[4 * q + k] = __fdiv_rn(1.0f, fmaxf(al, 1e-4f));
            if (__float_as_uint(ym[k]) < 0x7F800000u)
                acc += fabsf(__fsub_rn(al, ym[k]));
        }
    }
    for (int i = P4 * 4 + gid; i < P; i += stride) {
        float al = __fadd_rn(__fmul_rn(s, dpri[i]), tt);
        depth_out[i] = __fdiv_rn(1.0f, fmaxf(al, 1e-4f));
        float ym = g_ymask[i];
        if (__float_as_uint(ym) < 0x7F800000u)
            acc += fabsf(__fsub_rn(al, ym));
    }
    shf[t] = acc;
    __syncthreads();
    for (int off = 128; off; off >>= 1) {
        if (t < off) shf[t] += shf[t + off];
        __syncthreads();
    }
    if (t == 0) g_part[blockIdx.x] = shf[0];

    if (!is_last_block(7, gridDim.x)) return;

    double d = 0.0;
    for (int i = t; i < OUTB; i += 256) d += (double)g_part[i];
    shd[t] = d;
    __syncthreads();
    for (int off = 128; off; off >>= 1) {
        if (t < off) shd[t] += shd[t + off];
        __syncthreads();
    }
    if (t == 0) {
        int n = g_n_valid;
        int denom = (n > 1) ? n : 1;
        float l1 = (float)shd[0] / (float)denom;
        float loss = __fmul_rn(0.5f, l1);
        if (n < 100) loss = 0.0f;
        o[0] = loss;
        g_done[7] = 0u;
    }
}

// ------------------ launch ------------------
extern "C" void kernel_launch(void* const* d_in, const int* in_sizes, int n_in,
                              void* d_out, int out_size) {
    const float* dren = (const float*)d_in[0];
    const float* dpri = (const float*)d_in[1];
    float* o = (float*)d_out;
    int P = in_sizes[0];
    float* yout  = o + 1;
    float* dout2 = o + 1 + P;

    unsigned int kk[4], kp[4], ks[4];
    jax_split2_host(0u, 42u, kk);
    jax_split2_host(kk[0], kk[1], kp);
    jax_split2_host(kk[2], kk[3], ks);
    uint4 KP = make_uint4(kp[0], kp[1], kp[2], kp[3]);
    uint4 KS = make_uint4(ks[0], ks[1], ks[2], ks[3]);

    int NB = (P + 2047) / 2048;

    k_fused1<<<NB, 256>>>(dren, yout, P, NB);
    k_fused2<<<NB, 256>>>(P);
    k_h20s<<<HB, 256>>>(dpri, yout, P, KP, KS);
    k_hist1<<<HB, 256>>>(P, 0, 3, 3);
    k_hist1<<<HB, 256>>>(P, 1, 4, 4);
    k_hist1<<<HB, 256>>>(P, 2, 5, 5);
    k_count<<<CNTB, 256>>>();
    k_out<<<OUTB, 256>>>(dpri, dout2, o, P);
}

// round 14
// speedup vs baseline: 1.2871x; 1.0041x over previous
#include <cuda_runtime.h>
#include <cstdint>

#define JAX_PARTITIONABLE 1

#define MAXP   (1024*2048)
#define NBMAX  1024
#define ITERS  1000
#define SUBN   50000
#define CNTB   1000
#define CHUNK  4096          // elements per block (16 per thread)
#define NANF   0x7FC00000u

// ------------------ device scratch (self-cleaning) ------------------
__device__ int          g_n_valid;
__device__ int          g_bc[NBMAX];
__device__ int          g_idx[MAXP];
__device__ float        g_ymask[MAXP];          // y if mask else NaN
__device__ float        g_xsub[SUBN];
__device__ float        g_ysub[SUBN];
__device__ float        g_scales[ITERS];
__device__ float        g_shifts[ITERS];
__device__ int          g_counts[ITERS];        // zero invariant
__device__ unsigned int g_hist[6][2048];        // zero invariant
__device__ unsigned int g_done[8];              // zero invariant
__device__ unsigned int g_sel_prefix;
__device__ long long    g_sel_rank;
__device__ float        g_med;
__device__ float        g_dyn;
__device__ float        g_s;
__device__ float        g_t;
__device__ float        g_part[NBMAX];

// ------------------ threefry2x32 (bit-exact vs JAX) ------------------
__host__ __device__ __forceinline__ void tf2x32(unsigned int k0, unsigned int k1,
                                                unsigned int x0, unsigned int x1,
                                                unsigned int& o0, unsigned int& o1) {
    unsigned int ks2 = k0 ^ k1 ^ 0x1BD11BDAu;
    x0 += k0; x1 += k1;
#define TF_RND(r) { x0 += x1; x1 = (x1 << (r)) | (x1 >> (32 - (r))); x1 ^= x0; }
    TF_RND(13) TF_RND(15) TF_RND(26) TF_RND(6)
    x0 += k1;  x1 += ks2 + 1u;
    TF_RND(17) TF_RND(29) TF_RND(16) TF_RND(24)
    x0 += ks2; x1 += k0 + 2u;
    TF_RND(13) TF_RND(15) TF_RND(26) TF_RND(6)
    x0 += k0;  x1 += k1 + 3u;
    TF_RND(17) TF_RND(29) TF_RND(16) TF_RND(24)
    x0 += k1;  x1 += ks2 + 4u;
    TF_RND(13) TF_RND(15) TF_RND(26) TF_RND(6)
    x0 += ks2; x1 += k0 + 5u;
#undef TF_RND
    o0 = x0; o1 = x1;
}

__device__ __forceinline__ unsigned int jax_bits(unsigned int ka, unsigned int kb,
                                                 unsigned int e, unsigned int n) {
#if JAX_PARTITIONABLE
    unsigned int a, b;
    tf2x32(ka, kb, 0u, e, a, b);
    return a ^ b;
#else
    unsigned int h = n >> 1;
    unsigned int lane = (e < h) ? e : (e - h);
    unsigned int a, b;
    tf2x32(ka, kb, lane, lane + h, a, b);
    return (e < h) ? a : b;
#endif
}

static inline void jax_split2_host(unsigned int ka, unsigned int kb, unsigned int* o) {
#if JAX_PARTITIONABLE
    unsigned int a, b;
    tf2x32(ka, kb, 0u, 0u, a, b); o[0] = a; o[1] = b;
    tf2x32(ka, kb, 0u, 1u, a, b); o[2] = a; o[3] = b;
#else
    unsigned int a0, b0, a1, b1;
    tf2x32(ka, kb, 0u, 2u, a0, b0);
    tf2x32(ka, kb, 1u, 3u, a1, b1);
    o[0] = a0; o[1] = a1; o[2] = b0; o[3] = b1;
#endif
}

// NaN/inf-safe: isfinite is implied (NaN fails both compares, +-inf fails one)
__device__ __forceinline__ bool maskf(float d) {
    return (d > 0.1f) && (d < 100.0f);
}
__device__ __forceinline__ float y_of(float d) {
    return __fdiv_rn(1.0f, __fadd_rn(d, 1e-6f));
}
__device__ __forceinline__ unsigned int randint_off(unsigned int hb, unsigned int lb,
                                                    unsigned int span) {
    unsigned int m = 65536u % span;
    m = (m * m) % span;
    unsigned int off = (hb % span) * m + (lb % span);
    return off % span;
}

// exclusive scan over 256 threads via warp shuffles; wsh = shared int[8]
__device__ __forceinline__ int blk_scan256(int v, int* wsh) {
    int t = threadIdx.x, lane = t & 31, w = t >> 5;
    int incl = v;
#pragma unroll
    for (int off = 1; off < 32; off <<= 1) {
        int x = __shfl_up_sync(0xffffffffu, incl, off);
        if (lane >= off) incl += x;
    }
    if (lane == 31) wsh[w] = incl;
    __syncthreads();
    if (w == 0) {
        int s = (lane < 8) ? wsh[lane] : 0;
#pragma unroll
        for (int off = 1; off < 8; off <<= 1) {
            int x = __shfl_up_sync(0xffffffffu, s, off);
            if (lane >= off) s += x;
        }
        if (lane < 8) wsh[lane] = s;
    }
    __syncthreads();
    return (w ? wsh[w - 1] : 0) + incl - v;
}

__device__ __forceinline__ bool is_last_block(int id, unsigned int grid) {
    __threadfence();
    __shared__ unsigned int s_last;
    if (threadIdx.x == 0)
        s_last = (atomicAdd(&g_done[id], 1u) == grid - 1u) ? 1u : 0u;
    __syncthreads();
    return s_last != 0u;
}

__device__ __forceinline__ void lb_clean(int hi, int doneid, int nb) {
    __syncthreads();
    if (hi >= 0)
        for (int j = threadIdx.x; j < nb; j += 256) g_hist[hi][j] = 0u;
    if (threadIdx.x == 0) g_done[doneid] = 0u;
}

// parallel bin selection over g_hist[hi]; levels 0/1: 2048 bins, level 2: 1024
__device__ void choose_level(int level, int stage, int hi, int P) {
    __shared__ int wsh[8];
    __shared__ int sh_b;
    __shared__ long long sh_e;
    __shared__ int sh_next;
    __shared__ unsigned int sh_tot;
    __shared__ int sh_need;
    __shared__ unsigned int sh_selkey, sh_vb;
    __shared__ unsigned int red[256];

    int t = threadIdx.x;
    int nb = (level == 2) ? 1024 : 2048;
    int per = nb >> 8;
    unsigned int v[8];
    int sum = 0;
#pragma unroll
    for (int j = 0; j < 8; j++) {
        v[j] = (j < per) ? g_hist[hi][t * per + j] : 0u;
        sum += (int)v[j];
    }
    if (t == 0) { sh_b = -1; sh_next = nb; }
    __syncthreads();
    int excl = blk_scan256(sum, wsh);
    if (t == 255) sh_tot = (unsigned int)(excl + sum);
    __syncthreads();
    long long r = g_sel_rank;
    if (r >= (long long)excl && r < (long long)(excl + sum)) {
        long long c = excl;
        for (int j = 0; j < per; j++) {
            if (r < c + (long long)v[j]) { sh_b = t * per + j; sh_e = c; break; }
            c += (long long)v[j];
        }
    }
    __syncthreads();
    int b = sh_b;
    if (level == 2 && b >= 0) {
        for (int j = 0; j < per; j++) {
            int idx = t * per + j;
            if (idx > b && v[j]) { atomicMin(&sh_next, idx); break; }
        }
    }
    __syncthreads();
    if (t == 0) {
        long long e = sh_e;
        int bb = b;
        long long tot = (long long)sh_tot;
        if (bb < 0) { bb = nb - 1; e = tot; }   // degenerate n==0
        long long rl = r - e;
        g_sel_rank = rl;
        if (level == 0) g_sel_prefix = (unsigned int)bb;
        else if (level == 1) g_sel_prefix = (g_sel_prefix << 11) | (unsigned int)bb;
        else {
            unsigned int selkey = (g_sel_prefix << 10) | (unsigned int)bb;
            unsigned int eq = g_hist[hi][bb];
            int n = g_n_valid;
            int need = 0;
            unsigned int vb = selkey;
            if (!(n & 1)) {
                if (rl + 1 < (long long)eq) vb = selkey;
                else if (sh_next < nb)
                    vb = (g_sel_prefix << 10) | (unsigned int)sh_next;
                else need = 1;
            }
            sh_need = need; sh_selkey = selkey; sh_vb = vb;
        }
    }
    __syncthreads();
    if (level != 2) return;

    unsigned int selkey = sh_selkey;
    unsigned int vb;
    if (sh_need) {
        // rare fallback: min key strictly greater than selkey
        float med = g_med;
        unsigned int local = 0xFFFFFFFFu;
        for (int i = t; i < P; i += 256) {
            float ym = g_ymask[i];
            unsigned int kraw = __float_as_uint(ym);
            if (kraw >= 0x7F800000u) continue;
            unsigned int key = stage ? (__float_as_uint(__fsub_rn(ym, med)) & 0x7FFFFFFFu)
                                     : kraw;
            if (key > selkey && key < local) local = key;
        }
        red[t] = local;
        __syncthreads();
        for (int off = 128; off; off >>= 1) {
            if (t < off) red[t] = min(red[t], red[t + off]);
            __syncthreads();
        }
        vb = red[0];
    } else vb = sh_vb;

    if (t == 0) {
        int n = g_n_valid;
        float va = __uint_as_float(selkey);
        float med = (n & 1) ? va
            : __fadd_rn(__fmul_rn(va, 0.5f), __fmul_rn(__uint_as_float(vb), 0.5f));
        if (stage == 0) {
            g_med = med;
            g_sel_rank = (n > 0) ? (long long)((n - 1) / 2) : 0ll;
            g_sel_prefix = 0u;
        } else {
            float dyn = __fmul_rn(med, 0.5f);
            if (dyn < 1e-5f) dyn = 0.01f;
            g_dyn = dyn;
        }
    }
}

// ------------------ kernels ------------------
// div pass: y, yout (scalar; misaligned dest) + ymask (float4), count, L0s0 hist;
// LB: scan g_bc, set n_valid/rank, choose L0s0, clean
__global__ void __launch_bounds__(256)
k_fused1(const float* __restrict__ dren, float* __restrict__ yout, int P, int NB) {
    __shared__ unsigned int sh[2048];
    __shared__ int wsh[8];
    __shared__ int sh_tot;
    int t = threadIdx.x;
    for (int j = t; j < 2048; j += 256) sh[j] = 0u;
    __syncthreads();
    int s0 = blockIdx.x * CHUNK + t * 16;
    int cnt = 0;
    if (s0 + 16 <= P) {
        float4 q0 = *(const float4*)(dren + s0);
        float4 q1 = *(const float4*)(dren + s0 + 4);
        float4 q2 = *(const float4*)(dren + s0 + 8);
        float4 q3 = *(const float4*)(dren + s0 + 12);
        float dd[16] = {q0.x, q0.y, q0.z, q0.w, q1.x, q1.y, q1.z, q1.w,
                        q2.x, q2.y, q2.z, q2.w, q3.x, q3.y, q3.z, q3.w};
        float ym[16];
#pragma unroll
        for (int k = 0; k < 16; k++) {
            float y = y_of(dd[k]);
            yout[s0 + k] = y;
            bool m = maskf(dd[k]);
            ym[k] = m ? y : __uint_as_float(NANF);
            if (m) { cnt++; atomicAdd(&sh[__float_as_uint(y) >> 21], 1u); }
        }
#pragma unroll
        for (int j = 0; j < 4; j++)
            *(float4*)(g_ymask + s0 + 4 * j) =
                make_float4(ym[4 * j], ym[4 * j + 1], ym[4 * j + 2], ym[4 * j + 3]);
    } else {
        for (int i = s0; i < P && i < s0 + 16; i++) {
            float d = dren[i];
            float y = y_of(d);
            yout[i] = y;
            bool m = maskf(d);
            g_ymask[i] = m ? y : __uint_as_float(NANF);
            if (m) { cnt++; atomicAdd(&sh[__float_as_uint(y) >> 21], 1u); }
        }
    }
    int lane = t & 31, w = t >> 5;
    int v = cnt;
    for (int o = 16; o; o >>= 1) v += __shfl_down_sync(0xffffffffu, v, o);
    if (lane == 0) wsh[w] = v;
    __syncthreads();
    if (t == 0) {
        int s = 0;
        for (int j = 0; j < 8; j++) s += wsh[j];
        g_bc[blockIdx.x] = s;
    }
    __syncthreads();
    for (int j = t; j < 2048; j += 256)
        if (sh[j]) atomicAdd(&g_hist[0][j], sh[j]);

    if (!is_last_block(0, gridDim.x)) return;

    int b4[4]; int s = 0;
#pragma unroll
    for (int j = 0; j < 4; j++) {
        int ii = t * 4 + j;
        b4[j] = (ii < NB) ? g_bc[ii] : 0;
        s += b4[j];
    }
    int ex = blk_scan256(s, wsh);
    int run = ex;
#pragma unroll
    for (int j = 0; j < 4; j++) {
        int ii = t * 4 + j;
        if (ii < NB) g_bc[ii] = run;
        run += b4[j];
    }
    if (t == 255) sh_tot = ex + s;
    __syncthreads();
    if (t == 0) {
        int n = sh_tot;
        g_n_valid = n;
        g_sel_rank = (n > 0) ? (long long)((n - 1) / 2) : 0ll;
        g_sel_prefix = 0u;
    }
    __syncthreads();
    choose_level(0, 0, 0, P);
    lb_clean(0, 0, 2048);
}

// stage0 L1 hist from ymask (+ scatter if !dense); LB: choose L1s0, clean
// NaN keys can't match a valid prefix -> no explicit validity check in hist path.
__global__ void __launch_bounds__(256)
k_fused2(int P) {
    __shared__ unsigned int sh[2048];
    __shared__ int wsh[8];
    int t = threadIdx.x;
    for (int j = t; j < 2048; j += 256) sh[j] = 0u;
    unsigned int prefix = g_sel_prefix;
    bool dense = (g_n_valid == P);
    __syncthreads();
    int s0 = blockIdx.x * CHUNK + t * 16;
    if (s0 + 16 <= P) {
        unsigned int key[16];
#pragma unroll
        for (int j = 0; j < 4; j++) {
            float4 a = *(const float4*)(g_ymask + s0 + 4 * j);
            key[4 * j]     = __float_as_uint(a.x);
            key[4 * j + 1] = __float_as_uint(a.y);
            key[4 * j + 2] = __float_as_uint(a.z);
            key[4 * j + 3] = __float_as_uint(a.w);
        }
#pragma unroll
        for (int k = 0; k < 16; k++)
            if ((key[k] >> 21) == prefix) atomicAdd(&sh[(key[k] >> 10) & 2047u], 1u);
        if (!dense) {
            int cnt = 0;
            unsigned int bits = 0u;
#pragma unroll
            for (int k = 0; k < 16; k++)
                if (key[k] < 0x7F800000u) { cnt++; bits |= (1u << k); }
            int excl = blk_scan256(cnt, wsh);
            int wpos = g_bc[blockIdx.x] + excl;
#pragma unroll
            for (int k = 0; k < 16; k++)
                if ((bits >> k) & 1u) g_idx[wpos++] = s0 + k;
        }
    } else {
        int cnt = 0;
        unsigned int bits = 0u;
        for (int i = s0; i < P && i < s0 + 16; i++) {
            unsigned int key = __float_as_uint(g_ymask[i]);
            if (key < 0x7F800000u) { cnt++; bits |= (1u << (i - s0)); }
            if ((key >> 21) == prefix) atomicAdd(&sh[(key >> 10) & 2047u], 1u);
        }
        if (!dense) {
            int excl = blk_scan256(cnt, wsh);
            int wpos = g_bc[blockIdx.x] + excl;
            for (int k = 0; k < 16; k++)
                if ((bits >> k) & 1u) g_idx[wpos++] = s0 + k;
        }
    }
    __syncthreads();
    for (int j = t; j < 2048; j += 256)
        if (sh[j]) atomicAdd(&g_hist[1][j], sh[j]);

    if (!is_last_block(1, gridDim.x)) return;
    choose_level(1, 0, 1, P);
    lb_clean(1, 1, 2048);
}

// stage0 L2 hist (ymask; prefix test excludes NaN) + RANSAC sampling; LB: med
__global__ void __launch_bounds__(256)
k_h20s(const float* __restrict__ dpri, const float* __restrict__ yout,
       int P, uint4 KP, uint4 KS) {
    __shared__ unsigned int sh[1024];
    int t = threadIdx.x;
    int gid = blockIdx.x * 256 + t;
    for (int j = t; j < 1024; j += 256) sh[j] = 0u;
    unsigned int prefix = g_sel_prefix;
    unsigned int span = (unsigned int)g_n_valid;
    bool dense = (span == (unsigned int)P);
    __syncthreads();

    int s0 = blockIdx.x * CHUNK + t * 16;
    if (s0 + 16 <= P) {
        unsigned int key[16];
#pragma unroll
        for (int j = 0; j < 4; j++) {
            float4 a = *(const float4*)(g_ymask + s0 + 4 * j);
            key[4 * j]     = __float_as_uint(a.x);
            key[4 * j + 1] = __float_as_uint(a.y);
            key[4 * j + 2] = __float_as_uint(a.z);
            key[4 * j + 3] = __float_as_uint(a.w);
        }
#pragma unroll
        for (int k = 0; k < 16; k++)
            if ((key[k] >> 10) == prefix) atomicAdd(&sh[key[k] & 1023u], 1u);
    } else {
        for (int i = s0; i < P && i < s0 + 16; i++) {
            unsigned int key = __float_as_uint(g_ymask[i]);
            if ((key >> 10) == prefix) atomicAdd(&sh[key & 1023u], 1u);
        }
    }

    if (gid < SUBN) {
        if (span == 0u) { g_xsub[gid] = 0.f; g_ysub[gid] = 0.f; }
        else {
            unsigned int hb = jax_bits(KS.x, KS.y, (unsigned int)gid, SUBN);
            unsigned int lb = jax_bits(KS.z, KS.w, (unsigned int)gid, SUBN);
            unsigned int pos = randint_off(hb, lb, span);
            int si = dense ? (int)pos : g_idx[pos];
            g_xsub[gid] = dpri[si];
            g_ysub[gid] = yout[si];
        }
    }
    if (gid < ITERS) {
        unsigned int p0 = 0u, p1 = 0u;
        if (span != 0u) {
            p0 = randint_off(jax_bits(KP.x, KP.y, 2u * gid, 2u * ITERS),
                             jax_bits(KP.z, KP.w, 2u * gid, 2u * ITERS), span);
            p1 = randint_off(jax_bits(KP.x, KP.y, 2u * gid + 1u, 2u * ITERS),
                             jax_bits(KP.z, KP.w, 2u * gid + 1u, 2u * ITERS), span);
        }
        int i0 = (dense && span) ? (int)p0 : g_idx[p0];
        int i1 = (dense && span) ? (int)p1 : g_idx[p1];
        float x1 = dpri[i0], x2 = dpri[i1];
        float y1 = yout[i0], y2 = yout[i1];
        float sc = __fdiv_rn(__fsub_rn(y2, y1), __fadd_rn(__fsub_rn(x2, x1), 1e-8f));
        g_scales[gid] = sc;
        g_shifts[gid] = __fsub_rn(y1, __fmul_rn(sc, x1));
    }
    __syncthreads();
    for (int j = t; j < 1024; j += 256)
        if (sh[j]) atomicAdd(&g_hist[2][j], sh[j]);

    if (!is_last_block(2, gridDim.x)) return;
    choose_level(2, 0, 2, P);
    lb_clean(2, 2, 1024);
}

// stage1 hist pass. key = bits(|ym-med|) via FSUB + AND (fabs in bit domain).
// L0: NaN lands in bin 0x3FE, above all finite bins -> never selected, no check.
// L1/L2: NaN prefix never equals a selected finite prefix -> no check.
__global__ void __launch_bounds__(256)
k_hist1(int P, int level, int hi, int doneid) {
    __shared__ unsigned int sh[2048];
    int t = threadIdx.x;
    int nb = (level == 2) ? 1024 : 2048;
    for (int j = t; j < nb; j += 256) sh[j] = 0u;
    float med = g_med;
    unsigned int prefix = g_sel_prefix;
    __syncthreads();
    int s0 = blockIdx.x * CHUNK + t * 16;
    if (s0 + 16 <= P) {
        float ym[16];
#pragma unroll
        for (int j = 0; j < 4; j++) {
            float4 a = *(const float4*)(g_ymask + s0 + 4 * j);
            ym[4 * j] = a.x; ym[4 * j + 1] = a.y; ym[4 * j + 2] = a.z; ym[4 * j + 3] = a.w;
        }
#pragma unroll
        for (int k = 0; k < 16; k++) {
            unsigned int key = __float_as_uint(__fsub_rn(ym[k], med)) & 0x7FFFFFFFu;
            if (level == 0) atomicAdd(&sh[key >> 21], 1u);
            else if (level == 1) { if ((key >> 21) == prefix) atomicAdd(&sh[(key >> 10) & 2047u], 1u); }
            else { if ((key >> 10) == prefix) atomicAdd(&sh[key & 1023u], 1u); }
        }
    } else {
        for (int i = s0; i < P && i < s0 + 16; i++) {
            unsigned int key = __float_as_uint(__fsub_rn(g_ymask[i], med)) & 0x7FFFFFFFu;
            if (level == 0) atomicAdd(&sh[key >> 21], 1u);
            else if (level == 1) { if ((key >> 21) == prefix) atomicAdd(&sh[(key >> 10) & 2047u], 1u); }
            else { if ((key >> 10) == prefix) atomicAdd(&sh[key & 1023u], 1u); }
        }
    }
    __syncthreads();
    for (int j = t; j < nb; j += 256)
        if (sh[j]) atomicAdd(&g_hist[hi][j], sh[j]);

    if (!is_last_block(doneid, gridDim.x)) return;
    choose_level(level, 1, hi, P);
    lb_clean(hi, doneid, nb);
}

// RANSAC scoring; LB: argmax -> g_s,g_t, zero g_counts
__global__ void __launch_bounds__(256)
k_count() {
    __shared__ int wc[8][8];
    __shared__ int sc[256], si[256];
    int t = threadIdx.x;
    int hy = (blockIdx.x % 125) * 8;
    int seg = blockIdx.x / 125;
    int j0 = seg * (SUBN / 8), j1 = j0 + (SUBN / 8);
    float s[8], tv[8];
    int c[8] = {0, 0, 0, 0, 0, 0, 0, 0};
#pragma unroll
    for (int k = 0; k < 8; k++) { s[k] = g_scales[hy + k]; tv[k] = g_shifts[hy + k]; }
    float dyn = g_dyn;
    for (int j = j0 + t; j < j1; j += 256) {
        float x = g_xsub[j], yv = g_ysub[j];
#pragma unroll
        for (int k = 0; k < 8; k++) {
            float r = fabsf(__fsub_rn(__fadd_rn(__fmul_rn(s[k], x), tv[k]), yv));
            c[k] += (r < dyn) ? 1 : 0;
        }
    }
    int lane = t & 31, w = t >> 5;
#pragma unroll
    for (int k = 0; k < 8; k++) {
        int v = c[k];
        for (int o = 16; o; o >>= 1) v += __shfl_down_sync(0xffffffffu, v, o);
        if (lane == 0) wc[w][k] = v;
    }
    __syncthreads();
    if (t < 8) {
        int v = 0;
        for (int j = 0; j < 8; j++) v += wc[j][t];
        atomicAdd(&g_counts[hy + t], v);
    }

    if (!is_last_block(6, gridDim.x)) return;

    int best = -2, bidx = 0x7FFFFFFF;
    for (int i = t; i < ITERS; i += 256) {
        int cc = (g_scales[i] > 0.0f) ? g_counts[i] : -1;
        if (cc > best || (cc == best && i < bidx)) { best = cc; bidx = i; }
    }
    sc[t] = best; si[t] = bidx;
    __syncthreads();
    for (int off = 128; off; off >>= 1) {
        if (t < off) {
            if (sc[t + off] > sc[t] || (sc[t + off] == sc[t] && si[t + off] < si[t])) {
                sc[t] = sc[t + off]; si[t] = si[t + off];
            }
        }
        __syncthreads();
    }
    if (t == 0) {
        bool valid = sc[0] >= 0;
        float ss = valid ? g_scales[si[0]] : 1.0f;
        float tt = valid ? g_shifts[si[0]] : 0.0f;
        if (g_n_valid < 10) { ss = 1.0f; tt = 0.0f; }
        g_s = ss; g_t = tt;
    }
    __syncthreads();
    for (int i = t; i < ITERS; i += 256) g_counts[i] = 0;
    if (t == 0) g_done[6] = 0u;
}

// outputs (rcp.approx: pure-output value, tol 1e-3 >> ~1e-7 err) + loss; LB: final
__global__ void __launch_bounds__(256)
k_out(const float* __restrict__ dpri, float* __restrict__ depth_out,
      float* __restrict__ o, int P) {
    __shared__ float shf[256];
    __shared__ double shd[256];
    int t = threadIdx.x;
    float s = g_s, tt = g_t;
    float acc = 0.f;
    int s0 = blockIdx.x * CHUNK + t * 16;
    if (s0 + 16 <= P) {
        float ym[16], pp[16];
#pragma unroll
        for (int j = 0; j < 4; j++) {
            float4 a = *(const float4*)(g_ymask + s0 + 4 * j);
            float4 p = *(const float4*)(dpri + s0 + 4 * j);
            ym[4 * j] = a.x; ym[4 * j + 1] = a.y; ym[4 * j + 2] = a.z; ym[4 * j + 3] = a.w;
            pp[4 * j] = p.x; pp[4 * j + 1] = p.y; pp[4 * j + 2] = p.z; pp[4 * j + 3] = p.w;
        }
#pragma unroll
        for (int k = 0; k < 16; k++) {
            float al = __fadd_rn(__fmul_rn(s, pp[k]), tt);
            float r;
            asm("rcp.approx.f32 %0, %1;" : "=f"(r) : "f"(fmaxf(al, 1e-4f)));
            depth_out[s0 + k] = r;
            if (__float_as_uint(ym[k]) < 0x7F800000u)
                acc += fabsf(__fsub_rn(al, ym[k]));
        }
    } else {
        for (int i = s0; i < P && i < s0 + 16; i++) {
            float al = __fadd_rn(__fmul_rn(s, dpri[i]), tt);
            float r;
            asm("rcp.approx.f32 %0, %1;" : "=f"(r) : "f"(fmaxf(al, 1e-4f)));
            depth_out[i] = r;
            float ym = g_ymask[i];
            if (__float_as_uint(ym) < 0x7F800000u)
                acc += fabsf(__fsub_rn(al, ym));
        }
    }
    shf[t] = acc;
    __syncthreads();
    for (int off = 128; off; off >>= 1) {
        if (t < off) shf[t] += shf[t + off];
        __syncthreads();
    }
    if (t == 0) g_part[blockIdx.x] = shf[0];

    if (!is_last_block(7, gridDim.x)) return;

    double d = 0.0;
    for (int i = t; i < (int)gridDim.x; i += 256) d += (double)g_part[i];
    shd[t] = d;
    __syncthreads();
    for (int off = 128; off; off >>= 1) {
        if (t < off) shd[t] += shd[t + off];
        __syncthreads();
    }
    if (t == 0) {
        int n = g_n_valid;
        int denom = (n > 1) ? n : 1;
        float l1 = (float)shd[0] / (float)denom;
        float loss = __fmul_rn(0.5f, l1);
        if (n < 100) loss = 0.0f;
        o[0] = loss;
        g_done[7] = 0u;
    }
}

// ------------------ launch ------------------
extern "C" void kernel_launch(void* const* d_in, const int* in_sizes, int n_in,
                              void* d_out, int out_size) {
    const float* dren = (const float*)d_in[0];
    const float* dpri = (const float*)d_in[1];
    float* o = (float*)d_out;
    int P = in_sizes[0];
    float* yout  = o + 1;
    float* dout2 = o + 1 + P;

    unsigned int kk[4], kp[4], ks[4];
    jax_split2_host(0u, 42u, kk);
    jax_split2_host(kk[0], kk[1], kp);
    jax_split2_host(kk[2], kk[3], ks);
    uint4 KP = make_uint4(kp[0], kp[1], kp[2], kp[3]);
    uint4 KS = make_uint4(ks[0], ks[1], ks[2], ks[3]);

    int NB = (P + CHUNK - 1) / CHUNK;   // 512 for P=2M

    k_fused1<<<NB, 256>>>(dren, yout, P, NB);
    k_fused2<<<NB, 256>>>(P);
    k_h20s<<<NB, 256>>>(dpri, yout, P, KP, KS);
    k_hist1<<<NB, 256>>>(P, 0, 3, 3);
    k_hist1<<<NB, 256>>>(P, 1, 4, 4);
    k_hist1<<<NB, 256>>>(P, 2, 5, 5);
    k_count<<<CNTB, 256>>>();
    k_out<<<NB, 256>>>(dpri, dout2, o, P);
}